// round 3
// baseline (speedup 1.0000x reference)
#include <cuda_runtime.h>
#include <cuda_bf16.h>

#define TT 2000
#define NB 64
#define VV 1000
#define ROWS (TT * NB)
#define NEG_BIG (-1e30f)

// Scratch (no allocation allowed in kernel_launch)
__device__ int   g_argmax[ROWS];
__device__ float g_s[ROWS];   // maxlp = max(logsoftmax) = -log(sum exp(x - max))

// ---------------------------------------------------------------------------
// Kernel A: warp-per-row reduction over V=1000.
// Computes argmax (first occurrence), maxlp, writes default paths output.
// ---------------------------------------------------------------------------
__global__ __launch_bounds__(256) void rowreduce_kernel(
    const float* __restrict__ logits, float* __restrict__ out)
{
    const int row  = blockIdx.x * 8 + (threadIdx.x >> 5);  // row = t*NB + n
    const int lane = threadIdx.x & 31;

    const float4* __restrict__ p =
        reinterpret_cast<const float4*>(logits + (size_t)row * VV);

    // V=1000 floats = 250 float4; each lane takes indices lane + 32*j, j<8.
    float4 v[8];
#pragma unroll
    for (int j = 0; j < 8; j++) {
        int idx = lane + 32 * j;
        if (idx < 250) v[j] = p[idx];
        else           v[j] = make_float4(NEG_BIG, NEG_BIG, NEG_BIG, NEG_BIG);
    }

    // Per-lane max + argmax (strict > keeps first occurrence within lane;
    // lane index ordering is monotonic in global index).
    float m = NEG_BIG; int am = 0;
#pragma unroll
    for (int j = 0; j < 8; j++) {
        int base = (lane + 32 * j) * 4;
        float x;
        x = v[j].x; if (x > m) { m = x; am = base;     }
        x = v[j].y; if (x > m) { m = x; am = base + 1; }
        x = v[j].z; if (x > m) { m = x; am = base + 2; }
        x = v[j].w; if (x > m) { m = x; am = base + 3; }
    }
    // Warp-reduce (prefer larger value; on tie, smaller index = first occurrence)
#pragma unroll
    for (int off = 16; off; off >>= 1) {
        float om = __shfl_xor_sync(0xffffffffu, m,  off);
        int   oa = __shfl_xor_sync(0xffffffffu, am, off);
        if (om > m || (om == m && oa < am)) { m = om; am = oa; }
    }

    // Sum of exp(x - rowmax) from registers
    float s = 0.f;
#pragma unroll
    for (int j = 0; j < 8; j++) {
        s += __expf(v[j].x - m) + __expf(v[j].y - m)
           + __expf(v[j].z - m) + __expf(v[j].w - m);
    }
#pragma unroll
    for (int off = 16; off; off >>= 1)
        s += __shfl_xor_sync(0xffffffffu, s, off);

    if (lane == 0) {
        g_argmax[row] = am;
        g_s[row]      = -__logf(s);          // maxlp = max - lse = -log(sum)
        out[NB + row] = (float)am;           // default paths (t-major: row = t*NB+n)
    }
}

// ---------------------------------------------------------------------------
// Kernel B: one warp per batch element. Keep-mask + stream compaction + score.
// ---------------------------------------------------------------------------
__global__ __launch_bounds__(32) void compact_kernel(
    const int* __restrict__ in_lens, float* __restrict__ out)
{
    const int n    = blockIdx.x;
    const int lane = threadIdx.x;
    const int L    = in_lens[n];

    float score = 0.f;
    int base  = 0;   // number of kept elements so far == final out_len
    int carry = 0;   // argmax at (chunk_base - 1); unused at t==0

    for (int t0 = 0; t0 < TT; t0 += 32) {
        int  t     = t0 + lane;
        bool valid = (t < TT);
        int   a  = 0;
        float sv = 0.f;
        if (valid) {
            a  = g_argmax[t * NB + n];
            sv = g_s[t * NB + n];
        }
        int aprev = __shfl_up_sync(0xffffffffu, a, 1);
        if (lane == 0) aprev = carry;

        bool inm  = valid && (t < L);
        bool keep = inm && (a != 0) && (t == 0 || a != aprev);
        if (inm) score += sv;

        unsigned bal = __ballot_sync(0xffffffffu, keep);
        if (keep) {
            int pos = base + __popc(bal & ((1u << lane) - 1u));
            out[NB + pos * NB + n] = (float)a;   // overwrite compacted prefix
        }
        base += __popc(bal);
        carry = __shfl_sync(0xffffffffu, a, 31);
    }

#pragma unroll
    for (int off = 16; off; off >>= 1)
        score += __shfl_xor_sync(0xffffffffu, score, off);

    if (lane == 0) {
        out[n] = score;                        // score block
        out[NB + TT * NB + n] = (float)base;   // out_lens block
    }
}

extern "C" void kernel_launch(void* const* d_in, const int* in_sizes, int n_in,
                              void* d_out, int out_size)
{
    const float* logits  = (const float*)d_in[0];
    const int*   in_lens = (const int*)d_in[1];
    float*       out     = (float*)d_out;

    rowreduce_kernel<<<ROWS / 8, 256>>>(logits, out);
    compact_kernel<<<NB, 32>>>(in_lens, out);
}

// round 5
// speedup vs baseline: 1.4588x; 1.4588x over previous
#include <cuda_runtime.h>
#include <cuda_bf16.h>

#define TT 2000
#define NB 64
#define VV 1000
#define ROWS (TT * NB)
#define NEG_BIG (-1e30f)
#define TPB 256
#define KITER 8          // ceil(TT / TPB)
#define NWARP (TPB / 32)

// Scratch (no allocation allowed). n-major packed: lo32 = argmax, hi32 = s bits.
__device__ unsigned long long g_packed[NB * TT];

// ---------------------------------------------------------------------------
// Kernel A: warp-per-row reduction over V=1000.
// Computes argmax (first occurrence) + maxlp, writes packed transposed scratch
// and the default paths output.
// ---------------------------------------------------------------------------
__global__ __launch_bounds__(256) void rowreduce_kernel(
    const float* __restrict__ logits, float* __restrict__ out)
{
    const int row  = blockIdx.x * 8 + (threadIdx.x >> 5);  // row = t*NB + n
    const int lane = threadIdx.x & 31;

    const float4* __restrict__ p =
        reinterpret_cast<const float4*>(logits + (size_t)row * VV);

    // V=1000 floats = 250 float4; lane takes indices lane + 32*j, j<8.
    float4 v[8];
#pragma unroll
    for (int j = 0; j < 8; j++) {
        int idx = lane + 32 * j;
        if (idx < 250) v[j] = p[idx];
        else           v[j] = make_float4(NEG_BIG, NEG_BIG, NEG_BIG, NEG_BIG);
    }

    float m = NEG_BIG; int am = 0;
#pragma unroll
    for (int j = 0; j < 8; j++) {
        int base = (lane + 32 * j) * 4;
        float x;
        x = v[j].x; if (x > m) { m = x; am = base;     }
        x = v[j].y; if (x > m) { m = x; am = base + 1; }
        x = v[j].z; if (x > m) { m = x; am = base + 2; }
        x = v[j].w; if (x > m) { m = x; am = base + 3; }
    }
#pragma unroll
    for (int off = 16; off; off >>= 1) {
        float om = __shfl_xor_sync(0xffffffffu, m,  off);
        int   oa = __shfl_xor_sync(0xffffffffu, am, off);
        if (om > m || (om == m && oa < am)) { m = om; am = oa; }
    }

    float s = 0.f;
#pragma unroll
    for (int j = 0; j < 8; j++) {
        s += __expf(v[j].x - m) + __expf(v[j].y - m)
           + __expf(v[j].z - m) + __expf(v[j].w - m);
    }
#pragma unroll
    for (int off = 16; off; off >>= 1)
        s += __shfl_xor_sync(0xffffffffu, s, off);

    if (lane == 0) {
        float maxlp = -__logf(s);            // max - lse
        int t = row >> 6;                    // NB == 64
        int n = row & (NB - 1);
        g_packed[(size_t)n * TT + t] =
            ((unsigned long long)__float_as_uint(maxlp) << 32) | (unsigned)am;
        out[NB + row] = (float)am;           // default paths (t-major)
    }
}

// ---------------------------------------------------------------------------
// Kernel B: block-per-n parallel compaction + score.
// ---------------------------------------------------------------------------
__global__ __launch_bounds__(TPB) void compact_kernel(
    const int* __restrict__ in_lens, float* __restrict__ out)
{
    __shared__ int   sh_a[TPB];
    __shared__ int   sh_cnt[NWARP];
    __shared__ float sh_sc[NWARP];

    const int n    = blockIdx.x;
    const int tid  = threadIdx.x;
    const int lane = tid & 31;
    const int wid  = tid >> 5;
    const int L    = in_lens[n];
    const unsigned long long* __restrict__ gp = g_packed + (size_t)n * TT;

    // Prefetch all chunks (coalesced, MLP=8 — one overlapped DRAM round trip)
    unsigned long long v[KITER];
#pragma unroll
    for (int k = 0; k < KITER; k++) {
        int t = tid + TPB * k;
        v[k] = (t < TT) ? gp[t] : 0ULL;
    }

    float score = 0.f;
    int base  = 0;   // running kept count == final out_len
    int carry = 0;   // argmax at (chunk_base - 1)

#pragma unroll
    for (int k = 0; k < KITER; k++) {
        int   t = tid + TPB * k;
        int   a = (int)(unsigned)(v[k] & 0xffffffffu);
        float s = __uint_as_float((unsigned)(v[k] >> 32));

        __syncthreads();                 // protect sh_a/sh_cnt reuse
        sh_a[tid] = a;
        __syncthreads();

        int  aprev = (tid > 0) ? sh_a[tid - 1] : carry;
        bool valid = (t < TT);
        bool inm   = valid && (t < L);
        bool keep  = inm && (a != 0) && (t == 0 || a != aprev);
        if (inm) score += s;

        unsigned bal = __ballot_sync(0xffffffffu, keep);
        if (lane == 0) sh_cnt[wid] = __popc(bal);
        __syncthreads();

        int prefix = base;
#pragma unroll
        for (int w = 0; w < NWARP; w++) {
            int c = sh_cnt[w];
            if (w < wid) prefix += c;
            base += c;
        }
        if (keep) {
            int pos = prefix + __popc(bal & ((1u << lane) - 1u));
            out[NB + pos * NB + n] = (float)a;   // overwrite compacted prefix
        }
        carry = sh_a[TPB - 1];
    }

#pragma unroll
    for (int off = 16; off; off >>= 1)
        score += __shfl_xor_sync(0xffffffffu, score, off);
    if (lane == 0) sh_sc[wid] = score;
    __syncthreads();

    if (tid == 0) {
        float tot = 0.f;
#pragma unroll
        for (int w = 0; w < NWARP; w++) tot += sh_sc[w];
        out[n] = tot;                          // score
        out[NB + TT * NB + n] = (float)base;   // out_lens
    }
}

extern "C" void kernel_launch(void* const* d_in, const int* in_sizes, int n_in,
                              void* d_out, int out_size)
{
    const float* logits  = (const float*)d_in[0];
    const int*   in_lens = (const int*)d_in[1];
    float*       out     = (float*)d_out;

    rowreduce_kernel<<<ROWS / 8, 256>>>(logits, out);
    compact_kernel<<<NB, TPB>>>(in_lens, out);
}